// round 1
// baseline (speedup 1.0000x reference)
#include <cuda_runtime.h>

// ---------------------------------------------------------------------------
// EqProp relaxation on GB300 — round 1: fp32 SIMT fused dual-GEMM baseline.
//
// states: s0 = x (fixed), s1..s4 updated.
// forward: s_l = clip(s_{l-1} @ W_{l-1} + b_l)   (first layer uses RAW x)
// sweep l: ds  = -s_l + b_l + rho(s_{l-1}) @ W_{l-1} [+ rho(s_{l+1}) @ W_l^T]
//          s_l = clip(s_l + 0.3*ds)
// Since every updated state is already clipped, rho(s_l) == s_l for l>=1;
// only rho(x) needs one explicit clip into g_rx.
// ---------------------------------------------------------------------------

#define BATCHN  1024
#define D0      2048
#define D1      2048
#define D2      2048
#define D3      2048
#define D4      1000
#define N_RELAX 25
#define LR      0.3f

#define BM 128
#define BN 128
#define BK 8
#define TM 8
#define TN 8
#define NTHREADS 256

// Scratch state buffers (static device arrays — no allocation).
__device__ float g_rx[BATCHN * D0];
__device__ float g_s1[BATCHN * D1];
__device__ float g_s2[BATCHN * D2];
__device__ float g_s3[BATCHN * D3];
__device__ float g_s4[BATCHN * D4];

__global__ void clip_kernel(const float* __restrict__ x, float* __restrict__ y, int n) {
    int i = blockIdx.x * blockDim.x + threadIdx.x;
    if (i < n) {
        float v = x[i];
        y[i] = fminf(fmaxf(v, 0.0f), 1.0f);
    }
}

// Fused GEMM:
//   acc = A1[M,K1] @ B1[K1,N]            (NN, row-major)
//       + (A2 ? A2[M,K2] @ B2[N,K2]^T : 0)  (NT: C[m,n] += A2[m,k]*B2[n,k])
// mode 0 (forward): out = clip(acc + bias[n])
// mode 1 (sweep):   s = Sold[m,n]; out = clip(s + LR*(-s + bias[n] + acc))
__global__ __launch_bounds__(NTHREADS, 2)
void gemm_fused(const float* __restrict__ A1, const float* __restrict__ B1, int K1,
                const float* __restrict__ A2, const float* __restrict__ B2, int K2,
                const float* __restrict__ bias,
                const float* __restrict__ Sold,
                float* __restrict__ out,
                int N, int mode)
{
    __shared__ float As[BK][BM];
    __shared__ float Bs[BK][BN];

    const int tid = threadIdx.x;
    const int tr  = tid >> 4;        // 0..15
    const int tc  = tid & 15;        // 0..15
    const int m0  = blockIdx.y * BM;
    const int n0  = blockIdx.x * BN;

    float acc[TM][TN];
#pragma unroll
    for (int i = 0; i < TM; i++)
#pragma unroll
        for (int j = 0; j < TN; j++) acc[i][j] = 0.0f;

    // Load-index maps
    const int a_row = tid >> 1;          // 0..127
    const int a_col = (tid & 1) * 4;     // 0 or 4
    const int b_row = tid >> 5;          // 0..7   (NN B tile)
    const int b_col = (tid & 31) * 4;    // 0..124 (NN B tile)

    // -------- Phase 1: NN over K1 --------
    for (int k0 = 0; k0 < K1; k0 += BK) {
        float4 av = *reinterpret_cast<const float4*>(A1 + (size_t)(m0 + a_row) * K1 + k0 + a_col);
        As[a_col + 0][a_row] = av.x;
        As[a_col + 1][a_row] = av.y;
        As[a_col + 2][a_row] = av.z;
        As[a_col + 3][a_row] = av.w;

        int gn = n0 + b_col;
        const float* bp = B1 + (size_t)(k0 + b_row) * N + gn;
        float4 bv;
        if (gn + 3 < N) {
            bv = *reinterpret_cast<const float4*>(bp);
        } else {
            bv.x = (gn + 0 < N) ? bp[0] : 0.0f;
            bv.y = (gn + 1 < N) ? bp[1] : 0.0f;
            bv.z = (gn + 2 < N) ? bp[2] : 0.0f;
            bv.w = (gn + 3 < N) ? bp[3] : 0.0f;
        }
        *reinterpret_cast<float4*>(&Bs[b_row][b_col]) = bv;

        __syncthreads();
#pragma unroll
        for (int kk = 0; kk < BK; kk++) {
            float ra[TM], rb[TN];
#pragma unroll
            for (int i = 0; i < TM; i++) ra[i] = As[kk][tr * TM + i];
#pragma unroll
            for (int j = 0; j < TN; j++) rb[j] = Bs[kk][tc * TN + j];
#pragma unroll
            for (int i = 0; i < TM; i++)
#pragma unroll
                for (int j = 0; j < TN; j++) acc[i][j] += ra[i] * rb[j];
        }
        __syncthreads();
    }

    // -------- Phase 2: NT over K2 (optional) --------
    if (A2 != nullptr) {
        for (int k0 = 0; k0 < K2; k0 += BK) {
            float4 av = *reinterpret_cast<const float4*>(A2 + (size_t)(m0 + a_row) * K2 + k0 + a_col);
            As[a_col + 0][a_row] = av.x;
            As[a_col + 1][a_row] = av.y;
            As[a_col + 2][a_row] = av.z;
            As[a_col + 3][a_row] = av.w;

            int nr = n0 + a_row;   // output-column index (row of B2)
            float4 bv = make_float4(0.0f, 0.0f, 0.0f, 0.0f);
            if (nr < N)
                bv = *reinterpret_cast<const float4*>(B2 + (size_t)nr * K2 + k0 + a_col);
            Bs[a_col + 0][a_row] = bv.x;
            Bs[a_col + 1][a_row] = bv.y;
            Bs[a_col + 2][a_row] = bv.z;
            Bs[a_col + 3][a_row] = bv.w;

            __syncthreads();
#pragma unroll
            for (int kk = 0; kk < BK; kk++) {
                float ra[TM], rb[TN];
#pragma unroll
                for (int i = 0; i < TM; i++) ra[i] = As[kk][tr * TM + i];
#pragma unroll
                for (int j = 0; j < TN; j++) rb[j] = Bs[kk][tc * TN + j];
#pragma unroll
                for (int i = 0; i < TM; i++)
#pragma unroll
                    for (int j = 0; j < TN; j++) acc[i][j] += ra[i] * rb[j];
            }
            __syncthreads();
        }
    }

    // -------- Epilogue --------
#pragma unroll
    for (int i = 0; i < TM; i++) {
        int m = m0 + tr * TM + i;
#pragma unroll
        for (int j = 0; j < TN; j++) {
            int n = n0 + tc * TN + j;
            if (n < N) {
                float v = acc[i][j] + bias[n];
                if (mode == 1) {
                    float s = Sold[(size_t)m * N + n];
                    v = s + LR * (-s + v);   // s + LR*ds, matching reference order
                }
                out[(size_t)m * N + n] = fminf(fmaxf(v, 0.0f), 1.0f);
            }
        }
    }
}

static inline void launch_gemm(const float* A1, const float* B1, int K1,
                               const float* A2, const float* B2, int K2,
                               const float* bias, const float* Sold,
                               float* out, int N, int mode)
{
    dim3 grid((N + BN - 1) / BN, BATCHN / BM);
    gemm_fused<<<grid, NTHREADS>>>(A1, B1, K1, A2, B2, K2, bias, Sold, out, N, mode);
}

extern "C" void kernel_launch(void* const* d_in, const int* in_sizes, int n_in,
                              void* d_out, int out_size)
{
    const float* x  = (const float*)d_in[0];
    const float* W0 = (const float*)d_in[1];
    const float* W1 = (const float*)d_in[2];
    const float* W2 = (const float*)d_in[3];
    const float* W3 = (const float*)d_in[4];
    const float* b1 = (const float*)d_in[5];
    const float* b2 = (const float*)d_in[6];
    const float* b3 = (const float*)d_in[7];
    const float* b4 = (const float*)d_in[8];

    float *rx, *s1, *s2, *s3, *s4;
    cudaGetSymbolAddress((void**)&rx, g_rx);
    cudaGetSymbolAddress((void**)&s1, g_s1);
    cudaGetSymbolAddress((void**)&s2, g_s2);
    cudaGetSymbolAddress((void**)&s3, g_s3);
    cudaGetSymbolAddress((void**)&s4, g_s4);

    // rho(x) once (states s1..s4 are already clipped by construction)
    clip_kernel<<<(BATCHN * D0 + 255) / 256, 256>>>(x, rx, BATCHN * D0);

    // Forward initialization (first layer uses RAW x, per reference)
    launch_gemm(x,  W0, D0, nullptr, nullptr, 0, b1, nullptr, s1, D1, 0);
    launch_gemm(s1, W1, D1, nullptr, nullptr, 0, b2, nullptr, s2, D2, 0);
    launch_gemm(s2, W2, D2, nullptr, nullptr, 0, b3, nullptr, s3, D3, 0);
    launch_gemm(s3, W3, D3, nullptr, nullptr, 0, b4, nullptr, s4, D4, 0);

    // 25 Gauss-Seidel sweeps (sequential: each step uses freshly updated states)
    for (int it = 0; it < N_RELAX; it++) {
        // l=1: rho(x)@W0 + s2@W1^T
        launch_gemm(rx, W0, D0, s2, W1, D2, b1, s1, s1, D1, 1);
        // l=2: s1@W1 + s3@W2^T
        launch_gemm(s1, W1, D1, s3, W2, D3, b2, s2, s2, D2, 1);
        // l=3: s2@W2 + s4@W3^T   (K2 = 1000)
        launch_gemm(s2, W2, D2, s4, W3, D4, b3, s3, s3, D3, 1);
        // l=4: s3@W3 only
        float* out4 = (it == N_RELAX - 1) ? (float*)d_out : s4;
        launch_gemm(s3, W3, D3, nullptr, nullptr, 0, b4, s4, out4, D4, 1);
    }
}

// round 4
// speedup vs baseline: 2.9627x; 2.9627x over previous
#include <cuda_runtime.h>
#include <cuda_bf16.h>
#include <cstdint>

// ============================================================================
// EqProp relaxation — round 3: mma.sync (HMMA) bf16 split-precision GEMMs.
// tcgen05 is unavailable (harness targets compute_103, 'a' features rejected).
// Every GEMM: D += Ahi*Bhi + Alo*Bhi + Ahi*Blo  (fp32 accum in registers)
// A [M,K] row-major, B [N,K] row-major (K-major)  ->  mma row.col
// ============================================================================

#define BATCHN  1024
#define DHID    2048
#define DOUT    1000
#define DOUTP   1024
#define N_RELAX 25
#define LR      0.3f

#define BK      32
#define LDS_B   80          // bytes per SMEM row: (32+8) bf16
#define MAT_B   (128 * LDS_B)   // 10240 bytes per matrix tile
#define BUF_B   (4 * MAT_B)     // Ah, Al, Bh, Bl
#define SMEM_BYTES (2 * BUF_B)  // double buffer = 81920

__device__ __forceinline__ uint32_t smem_u32(const void* p) {
    uint32_t a;
    asm("{ .reg .u64 t; cvta.to.shared.u64 t, %1; cvt.u32.u64 %0, t; }" : "=r"(a) : "l"(p));
    return a;
}

#define CP16(dst, src) asm volatile("cp.async.cg.shared.global [%0], [%1], 16;" :: "r"(dst), "l"(src) : "memory")
#define CP_COMMIT()    asm volatile("cp.async.commit_group;" ::: "memory")
#define CP_WAIT0()     asm volatile("cp.async.wait_group 0;" ::: "memory")

#define LDSM4(r, a) \
    asm volatile("ldmatrix.sync.aligned.m8n8.x4.shared.b16 {%0,%1,%2,%3}, [%4];" \
                 : "=r"((r)[0]), "=r"((r)[1]), "=r"((r)[2]), "=r"((r)[3]) : "r"(a))

#define MMA16816(c, a, b0, b1) \
    asm volatile("mma.sync.aligned.m16n8k16.row.col.f32.bf16.bf16.f32 " \
                 "{%0,%1,%2,%3},{%4,%5,%6,%7},{%8,%9},{%0,%1,%2,%3};" \
                 : "+f"((c)[0]), "+f"((c)[1]), "+f"((c)[2]), "+f"((c)[3]) \
                 : "r"((a)[0]), "r"((a)[1]), "r"((a)[2]), "r"((a)[3]), "r"(b0), "r"(b1))

// --- static device storage ---------------------------------------------------
#define MEL 1048576
__device__ __nv_bfloat16 g_bf[70u * MEL];
__device__ float g_f[6u * MEL + 1024u * 1000u];

#define OFF_XH   (0u)
#define OFF_XL   (2u*MEL)
#define OFF_RXH  (4u*MEL)
#define OFF_RXL  (6u*MEL)
#define OFF_S1H  (8u*MEL)
#define OFF_S1L  (10u*MEL)
#define OFF_S2H  (12u*MEL)
#define OFF_S2L  (14u*MEL)
#define OFF_S3H  (16u*MEL)
#define OFF_S3L  (18u*MEL)
#define OFF_S4H  (20u*MEL)
#define OFF_S4L  (21u*MEL)
#define OFF_WT0H (22u*MEL)
#define OFF_WT0L (26u*MEL)
#define OFF_WT1H (30u*MEL)
#define OFF_WT1L (34u*MEL)
#define OFF_WT2H (38u*MEL)
#define OFF_WT2L (42u*MEL)
#define OFF_WT3H (46u*MEL)
#define OFF_WT3L (48u*MEL)
#define OFF_W1H  (50u*MEL)
#define OFF_W1L  (54u*MEL)
#define OFF_W2H  (58u*MEL)
#define OFF_W2L  (62u*MEL)
#define OFF_W3H  (66u*MEL)
#define OFF_W3L  (68u*MEL)
#define OFF_S1F  (0u)
#define OFF_S2F  (2u*MEL)
#define OFF_S3F  (4u*MEL)
#define OFF_S4F  (6u*MEL)

// --- conversion kernels ------------------------------------------------------
__device__ __forceinline__ void split2(float v, __nv_bfloat16& h, __nv_bfloat16& l) {
    h = __float2bfloat16(v);
    l = __float2bfloat16(v - __bfloat162float(h));
}

__global__ void convert_x_kernel(const float* __restrict__ x,
                                 __nv_bfloat16* xh, __nv_bfloat16* xl,
                                 __nv_bfloat16* rxh, __nv_bfloat16* rxl, int n) {
    int i = blockIdx.x * blockDim.x + threadIdx.x;
    if (i < n) {
        float v = x[i];
        __nv_bfloat16 h, l;
        split2(v, h, l); xh[i] = h; xl[i] = l;
        float c = fminf(fmaxf(v, 0.0f), 1.0f);
        split2(c, h, l); rxh[i] = h; rxl[i] = l;
    }
}

__global__ void convert_w_kernel(const float* __restrict__ W, int R, int C, int Cpad,
                                 __nv_bfloat16* oh, __nv_bfloat16* ol) {
    int i = blockIdx.x * blockDim.x + threadIdx.x;
    if (i < R * Cpad) {
        int r = i / Cpad, c = i - r * Cpad;
        float v = (c < C) ? W[(size_t)r * C + c] : 0.0f;
        __nv_bfloat16 h, l;
        split2(v, h, l); oh[i] = h; ol[i] = l;
    }
}

__global__ void transpose_w_kernel(const float* __restrict__ W, int R, int C, int Cpad,
                                   __nv_bfloat16* oh, __nv_bfloat16* ol) {
    __shared__ float t[32][33];
    int r0 = blockIdx.x * 32;
    int c0 = blockIdx.y * 32;
    int tx = threadIdx.x, ty = threadIdx.y;
#pragma unroll
    for (int i = 0; i < 4; i++) {
        int r = r0 + ty + i * 8, c = c0 + tx;
        t[ty + i * 8][tx] = (c < C) ? W[(size_t)r * C + c] : 0.0f;
    }
    __syncthreads();
#pragma unroll
    for (int i = 0; i < 4; i++) {
        int c = c0 + ty + i * 8;
        int r = r0 + tx;
        if (c < Cpad) {
            float v = t[tx][ty + i * 8];
            __nv_bfloat16 h, l;
            split2(v, h, l);
            oh[(size_t)c * R + r] = h;
            ol[(size_t)c * R + r] = l;
        }
    }
}

// --- main GEMM kernel --------------------------------------------------------
__global__ void __launch_bounds__(256, 1)
eqprop_gemm(const __nv_bfloat16* __restrict__ A1h, const __nv_bfloat16* __restrict__ A1l, int K1,
            const __nv_bfloat16* __restrict__ B1h, const __nv_bfloat16* __restrict__ B1l,
            const __nv_bfloat16* __restrict__ A2h, const __nv_bfloat16* __restrict__ A2l, int K2,
            const __nv_bfloat16* __restrict__ B2h, const __nv_bfloat16* __restrict__ B2l,
            const float* __restrict__ bias, const float* __restrict__ Sold,
            float* __restrict__ outf, __nv_bfloat16* __restrict__ outh,
            __nv_bfloat16* __restrict__ outl,
            int Nreal, int Npad, int mode)
{
    extern __shared__ char smem[];
    const uint32_t sbase = smem_u32(smem);
    const int tid  = threadIdx.x;
    const int wid  = tid >> 5, lane = tid & 31;
    const int wm   = wid >> 2;          // 0..1
    const int wn   = wid & 3;           // 0..3
    const int m0   = blockIdx.y * 128;
    const int n0   = blockIdx.x * 128;

    float acc[4][4][4];
#pragma unroll
    for (int i = 0; i < 4; i++)
#pragma unroll
        for (int j = 0; j < 4; j++)
#pragma unroll
            for (int q = 0; q < 4; q++) acc[i][j][q] = 0.0f;

    const int nch1 = K1 >> 5;
    const int nch2 = K2 >> 5;
    const int nch  = nch1 + nch2;

    // cp.async map: 2048 x 16B per chunk, 8 per thread
    auto issue_loads = [&](int c, int st) {
        const __nv_bfloat16 *pah, *pal, *pbh, *pbl;
        int ld, k0;
        if (c < nch1) { pah = A1h; pal = A1l; pbh = B1h; pbl = B1l; ld = K1; k0 = c << 5; }
        else          { pah = A2h; pal = A2l; pbh = B2h; pbl = B2l; ld = K2; k0 = (c - nch1) << 5; }
        const uint32_t stb = sbase + st * BUF_B;
#pragma unroll
        for (int j = 0; j < 2; j++) {
            int v  = tid + (j << 8);     // 0..511 over one matrix shape
            int r  = v >> 2;             // row 0..127
            int qc = v & 3;              // 16B quarter
            uint32_t soff = (uint32_t)(r * LDS_B + qc * 16);
            size_t aoff = (size_t)(m0 + r) * ld + k0 + qc * 8;
            size_t boff = (size_t)(n0 + r) * ld + k0 + qc * 8;
            CP16(stb + 0 * MAT_B + soff, pah + aoff);
            CP16(stb + 1 * MAT_B + soff, pal + aoff);
            CP16(stb + 2 * MAT_B + soff, pbh + boff);
            CP16(stb + 3 * MAT_B + soff, pbl + boff);
        }
    };

    // ldmatrix lane-address precompute
    const int lt  = lane >> 3;     // tile group 0..3
    const int lr  = lane & 7;      // row within tile
    // A tiles: t0:(r+0,k+0) t1:(r+8,k+0) t2:(r+0,k+16B) t3:(r+8,k+16B)
    const uint32_t a_lane_off = (uint32_t)((wm * 64 + (lt & 1) * 8 + lr) * LDS_B + (lt >> 1) * 16);
    // B tiles: t0:(n+0,k+0) t1:(n+0,k+16B) t2:(n+8,k+0) t3:(n+8,k+16B)
    const uint32_t b_lane_off = (uint32_t)((wn * 32 + (lt >> 1) * 8 + lr) * LDS_B + (lt & 1) * 16);

    issue_loads(0, 0);
    CP_COMMIT();

    for (int i = 0; i < nch; i++) {
        CP_WAIT0();
        __syncthreads();
        if (i + 1 < nch) { issue_loads(i + 1, (i + 1) & 1); CP_COMMIT(); }

        const uint32_t stb = sbase + (i & 1) * BUF_B;
        const uint32_t sAh = stb + 0 * MAT_B + a_lane_off;
        const uint32_t sAl = stb + 1 * MAT_B + a_lane_off;
        const uint32_t sBh = stb + 2 * MAT_B + b_lane_off;
        const uint32_t sBl = stb + 3 * MAT_B + b_lane_off;

#pragma unroll
        for (int k16 = 0; k16 < 2; k16++) {
            const uint32_t kb = k16 * 32;
            uint32_t ah[4][4], al[4][4];
#pragma unroll
            for (int mt = 0; mt < 4; mt++) {
                LDSM4(ah[mt], sAh + mt * (16 * LDS_B) + kb);
                LDSM4(al[mt], sAl + mt * (16 * LDS_B) + kb);
            }
            uint32_t bh[2][4], bl[2][4];
#pragma unroll
            for (int pr = 0; pr < 2; pr++) {
                LDSM4(bh[pr], sBh + pr * (16 * LDS_B) + kb);
                LDSM4(bl[pr], sBl + pr * (16 * LDS_B) + kb);
            }
#pragma unroll
            for (int mt = 0; mt < 4; mt++) {
#pragma unroll
                for (int nt = 0; nt < 4; nt++) {
                    const int pr = nt >> 1, hx = (nt & 1) * 2;
                    MMA16816(acc[mt][nt], ah[mt], bh[pr][hx], bh[pr][hx + 1]);
                    MMA16816(acc[mt][nt], al[mt], bh[pr][hx], bh[pr][hx + 1]);
                    MMA16816(acc[mt][nt], ah[mt], bl[pr][hx], bl[pr][hx + 1]);
                }
            }
        }
        __syncthreads();
    }

    // ---- epilogue ----
#pragma unroll
    for (int mt = 0; mt < 4; mt++) {
#pragma unroll
        for (int nt = 0; nt < 4; nt++) {
            const int n = n0 + wn * 32 + nt * 8 + ((lane & 3) << 1);
#pragma unroll
            for (int half = 0; half < 2; half++) {
                const int m = m0 + wm * 64 + mt * 16 + (lane >> 2) + half * 8;
#pragma unroll
                for (int e = 0; e < 2; e++) {
                    const int nn = n + e;
                    float v = acc[mt][nt][half * 2 + e];
                    float r;
                    if (nn < Nreal) {
                        float bb = bias[nn];
                        if (mode == 0) {
                            r = v + bb;
                        } else {
                            float s = Sold[(size_t)m * Nreal + nn];
                            r = s + LR * (bb + v - s);
                        }
                        r = fminf(fmaxf(r, 0.0f), 1.0f);
                        outf[(size_t)m * Nreal + nn] = r;
                    } else {
                        r = 0.0f;
                    }
                    if (nn < Npad) {
                        __nv_bfloat16 h, l;
                        split2(r, h, l);
                        outh[(size_t)m * Npad + nn] = h;
                        outl[(size_t)m * Npad + nn] = l;
                    }
                }
            }
        }
    }
}

// --- host orchestration ------------------------------------------------------
static void launch_gemm(const __nv_bfloat16* A1h, const __nv_bfloat16* A1l, int K1,
                        const __nv_bfloat16* B1h, const __nv_bfloat16* B1l,
                        const __nv_bfloat16* A2h, const __nv_bfloat16* A2l, int K2,
                        const __nv_bfloat16* B2h, const __nv_bfloat16* B2l,
                        const float* bias, const float* Sold,
                        float* outf, __nv_bfloat16* outh, __nv_bfloat16* outl,
                        int Nreal, int Npad, int mode)
{
    dim3 grid(Npad / 128, BATCHN / 128);
    eqprop_gemm<<<grid, 256, SMEM_BYTES>>>(A1h, A1l, K1, B1h, B1l, A2h, A2l, K2, B2h, B2l,
                                           bias, Sold, outf, outh, outl, Nreal, Npad, mode);
}

extern "C" void kernel_launch(void* const* d_in, const int* in_sizes, int n_in,
                              void* d_out, int out_size)
{
    const float* x  = (const float*)d_in[0];
    const float* W0 = (const float*)d_in[1];
    const float* W1 = (const float*)d_in[2];
    const float* W2 = (const float*)d_in[3];
    const float* W3 = (const float*)d_in[4];
    const float* b1 = (const float*)d_in[5];
    const float* b2 = (const float*)d_in[6];
    const float* b3 = (const float*)d_in[7];
    const float* b4 = (const float*)d_in[8];

    cudaFuncSetAttribute(eqprop_gemm, cudaFuncAttributeMaxDynamicSharedMemorySize, SMEM_BYTES);

    __nv_bfloat16* bf;
    float* fp;
    cudaGetSymbolAddress((void**)&bf, g_bf);
    cudaGetSymbolAddress((void**)&fp, g_f);

    __nv_bfloat16 *xh = bf + OFF_XH,  *xl = bf + OFF_XL;
    __nv_bfloat16 *rxh = bf + OFF_RXH, *rxl = bf + OFF_RXL;
    __nv_bfloat16 *s1h = bf + OFF_S1H, *s1l = bf + OFF_S1L;
    __nv_bfloat16 *s2h = bf + OFF_S2H, *s2l = bf + OFF_S2L;
    __nv_bfloat16 *s3h = bf + OFF_S3H, *s3l = bf + OFF_S3L;
    __nv_bfloat16 *s4h = bf + OFF_S4H, *s4l = bf + OFF_S4L;
    __nv_bfloat16 *wt0h = bf + OFF_WT0H, *wt0l = bf + OFF_WT0L;
    __nv_bfloat16 *wt1h = bf + OFF_WT1H, *wt1l = bf + OFF_WT1L;
    __nv_bfloat16 *wt2h = bf + OFF_WT2H, *wt2l = bf + OFF_WT2L;
    __nv_bfloat16 *wt3h = bf + OFF_WT3H, *wt3l = bf + OFF_WT3L;
    __nv_bfloat16 *w1h = bf + OFF_W1H, *w1l = bf + OFF_W1L;
    __nv_bfloat16 *w2h = bf + OFF_W2H, *w2l = bf + OFF_W2L;
    __nv_bfloat16 *w3h = bf + OFF_W3H, *w3l = bf + OFF_W3L;
    float *s1f = fp + OFF_S1F, *s2f = fp + OFF_S2F, *s3f = fp + OFF_S3F, *s4f = fp + OFF_S4F;

    {
        int n = BATCHN * DHID;
        convert_x_kernel<<<(n + 255) / 256, 256>>>(x, xh, xl, rxh, rxl, n);
    }
    dim3 tb(32, 8);
    transpose_w_kernel<<<dim3(DHID / 32, DHID / 32),  tb>>>(W0, DHID, DHID, DHID,  wt0h, wt0l);
    transpose_w_kernel<<<dim3(DHID / 32, DHID / 32),  tb>>>(W1, DHID, DHID, DHID,  wt1h, wt1l);
    transpose_w_kernel<<<dim3(DHID / 32, DHID / 32),  tb>>>(W2, DHID, DHID, DHID,  wt2h, wt2l);
    transpose_w_kernel<<<dim3(DHID / 32, DOUTP / 32), tb>>>(W3, DHID, DOUT, DOUTP, wt3h, wt3l);
    {
        int n = DHID * DHID;
        convert_w_kernel<<<(n + 255) / 256, 256>>>(W1, DHID, DHID, DHID, w1h, w1l);
        convert_w_kernel<<<(n + 255) / 256, 256>>>(W2, DHID, DHID, DHID, w2h, w2l);
        int n3 = DHID * DOUTP;
        convert_w_kernel<<<(n3 + 255) / 256, 256>>>(W3, DHID, DOUT, DOUTP, w3h, w3l);
    }

    // ---- forward init (layer 1 uses RAW x) ----
    launch_gemm(xh,  xl,  DHID, wt0h, wt0l, nullptr, nullptr, 0, nullptr, nullptr,
                b1, nullptr, s1f, s1h, s1l, DHID, DHID, 0);
    launch_gemm(s1h, s1l, DHID, wt1h, wt1l, nullptr, nullptr, 0, nullptr, nullptr,
                b2, nullptr, s2f, s2h, s2l, DHID, DHID, 0);
    launch_gemm(s2h, s2l, DHID, wt2h, wt2l, nullptr, nullptr, 0, nullptr, nullptr,
                b3, nullptr, s3f, s3h, s3l, DHID, DHID, 0);
    launch_gemm(s3h, s3l, DHID, wt3h, wt3l, nullptr, nullptr, 0, nullptr, nullptr,
                b4, nullptr, s4f, s4h, s4l, DOUT, DOUTP, 0);

    // ---- 25 Gauss-Seidel sweeps ----
    for (int it = 0; it < N_RELAX; it++) {
        launch_gemm(rxh, rxl, DHID, wt0h, wt0l, s2h, s2l, DHID, w1h, w1l,
                    b1, s1f, s1f, s1h, s1l, DHID, DHID, 1);
        launch_gemm(s1h, s1l, DHID, wt1h, wt1l, s3h, s3l, DHID, w2h, w2l,
                    b2, s2f, s2f, s2h, s2l, DHID, DHID, 1);
        launch_gemm(s2h, s2l, DHID, wt2h, wt2l, s4h, s4l, DOUTP, w3h, w3l,
                    b3, s3f, s3f, s3h, s3l, DHID, DHID, 1);
        float* out4 = (it == N_RELAX - 1) ? (float*)d_out : s4f;
        launch_gemm(s3h, s3l, DHID, wt3h, wt3l, nullptr, nullptr, 0, nullptr, nullptr,
                    b4, s4f, out4, s4h, s4l, DOUT, DOUTP, 1);
    }
}